// round 17
// baseline (speedup 1.0000x reference)
#include <cuda_runtime.h>

// SidedDistance via uniform spatial grid: argmin_j ||S1[b,n]-S2[b,j]||^2,
// B=4, N=M=8192. Output = float32 indices.
//
// Exactness: every examined candidate is scored with the R8-validated bit-exact
// reference lowering:
//   n  = fl(fl(x^2)+fl(y^2))+fl(z^2)   (each op rounded once)
//   cr = fma(az,z, fma(ay,y, fl(ax*x)))
//   d  = fl(fma(cr,-2,n1) + n2)        (== fl(fl(n1-2cr)+n2), 2cr exact)
// Winner = lexicographic min of (d, original index) => np.argmin first-index ties.
//
// Completeness: cells at Chebyshev ring k from the query's (clamped) cell contain
// only points at true distance >= (k-1)*hmin. hmin is shrunk (x(1-1e-5)) and the
// stop test is bound^2 > best + 1e-4, dwarfing the ~1e-6 fp error of d, so no
// candidate with d <= best (including exact ties) can be outside examined rings.

#define NBATCH 4
#define NQ     8192
#define M      8192
#define GRID   16
#define NCELL  (GRID * GRID * GRID)    // 4096
#define BT     1024                    // binning block threads
#define CPT    (M / BT)                // 8 candidates per binning thread
#define QT     256                     // query block threads
#define SAFETY 1e-4f

__device__ float4 g_sorted[NBATCH][M];          // {x, y, z, bitcast(orig idx)}
__device__ int    g_start[NBATCH][NCELL + 1];   // exclusive starts
__device__ float  g_params[NBATCH][8];          // ox,oy,oz, ivx,ivy,ivz, hmin

// ---------------- Kernel 1: per-batch bbox + bin + scan + scatter ----------------
__global__ __launch_bounds__(BT, 1)
void grid_build(const float* __restrict__ S2)
{
    __shared__ float sred[BT];
    __shared__ int   hist[NCELL];       // 16 KB
    __shared__ int   scanbuf[BT];
    __shared__ float sp[7];             // ox,oy,oz,ivx,ivy,ivz,hmin

    const int b = blockIdx.x;
    const int t = threadIdx.x;
    const float* s2b = S2 + (size_t)b * M * 3;

    // load this thread's 8 candidates
    float cx[CPT], cy[CPT], cz[CPT];
#pragma unroll
    for (int i = 0; i < CPT; ++i) {
        const int j = t + i * BT;
        cx[i] = s2b[3 * j + 0];
        cy[i] = s2b[3 * j + 1];
        cz[i] = s2b[3 * j + 2];
    }

    // ---- bbox: 6 tree reductions ----
    float lmin[3], lmax[3];
    {
        float mnx = cx[0], mxx = cx[0], mny = cy[0], mxy = cy[0], mnz = cz[0], mxz = cz[0];
#pragma unroll
        for (int i = 1; i < CPT; ++i) {
            mnx = fminf(mnx, cx[i]); mxx = fmaxf(mxx, cx[i]);
            mny = fminf(mny, cy[i]); mxy = fmaxf(mxy, cy[i]);
            mnz = fminf(mnz, cz[i]); mxz = fmaxf(mxz, cz[i]);
        }
        lmin[0] = mnx; lmin[1] = mny; lmin[2] = mnz;
        lmax[0] = mxx; lmax[1] = mxy; lmax[2] = mxz;
    }
    float bmin[3], bmax[3];
    for (int a = 0; a < 3; ++a) {
        sred[t] = lmin[a]; __syncthreads();
        for (int s = BT / 2; s > 0; s >>= 1) {
            if (t < s) sred[t] = fminf(sred[t], sred[t + s]);
            __syncthreads();
        }
        bmin[a] = sred[0]; __syncthreads();
        sred[t] = lmax[a]; __syncthreads();
        for (int s = BT / 2; s > 0; s >>= 1) {
            if (t < s) sred[t] = fmaxf(sred[t], sred[t + s]);
            __syncthreads();
        }
        bmax[a] = sred[0]; __syncthreads();
    }

    if (t == 0) {
        float w[3], iv[3];
        for (int a = 0; a < 3; ++a) {
            w[a]  = fmaxf(bmax[a] - bmin[a], 1e-20f);
            iv[a] = (float)GRID / (w[a] * (1.0f + 1e-5f));
        }
        float hmin = fminf(fminf(w[0], w[1]), w[2]) * (1.0f - 1e-5f) / (float)GRID;
        sp[0] = bmin[0]; sp[1] = bmin[1]; sp[2] = bmin[2];
        sp[3] = iv[0];   sp[4] = iv[1];   sp[5] = iv[2];
        sp[6] = hmin;
        g_params[b][0] = bmin[0]; g_params[b][1] = bmin[1]; g_params[b][2] = bmin[2];
        g_params[b][3] = iv[0];   g_params[b][4] = iv[1];   g_params[b][5] = iv[2];
        g_params[b][6] = hmin;
    }
    // zero histogram
    for (int i = t; i < NCELL; i += BT) hist[i] = 0;
    __syncthreads();

    // ---- histogram ----
    const float ox = sp[0], oy = sp[1], oz = sp[2];
    const float ivx = sp[3], ivy = sp[4], ivz = sp[5];
    int cid[CPT];
#pragma unroll
    for (int i = 0; i < CPT; ++i) {
        int icx = min(GRID - 1, max(0, (int)floorf((cx[i] - ox) * ivx)));
        int icy = min(GRID - 1, max(0, (int)floorf((cy[i] - oy) * ivy)));
        int icz = min(GRID - 1, max(0, (int)floorf((cz[i] - oz) * ivz)));
        cid[i] = (icz * GRID + icy) * GRID + icx;
        atomicAdd(&hist[cid[i]], 1);
    }
    __syncthreads();

    // ---- exclusive scan of hist[4096] (4 per thread + Hillis-Steele over 1024) ----
    int h0 = hist[4 * t + 0], h1 = hist[4 * t + 1], h2 = hist[4 * t + 2], h3 = hist[4 * t + 3];
    int tsum = h0 + h1 + h2 + h3;
    scanbuf[t] = tsum;
    __syncthreads();
    for (int off = 1; off < BT; off <<= 1) {
        int v = (t >= off) ? scanbuf[t - off] : 0;
        __syncthreads();
        scanbuf[t] += v;
        __syncthreads();
    }
    int base = scanbuf[t] - tsum;     // exclusive across thread groups
    int s0 = base;
    int s1 = s0 + h0;
    int s2 = s1 + h1;
    int s3 = s2 + h2;
    hist[4 * t + 0] = s0; g_start[b][4 * t + 0] = s0;
    hist[4 * t + 1] = s1; g_start[b][4 * t + 1] = s1;
    hist[4 * t + 2] = s2; g_start[b][4 * t + 2] = s2;
    hist[4 * t + 3] = s3; g_start[b][4 * t + 3] = s3;
    if (t == 0) g_start[b][NCELL] = M;
    __syncthreads();

    // ---- scatter (hist now = cursors) ----
#pragma unroll
    for (int i = 0; i < CPT; ++i) {
        const int j = t + i * BT;
        int slot = atomicAdd(&hist[cid[i]], 1);
        g_sorted[b][slot] = make_float4(cx[i], cy[i], cz[i], __int_as_float(j));
    }
}

// ---------------- Kernel 2: thread-per-query ring search ----------------
__global__ __launch_bounds__(QT, 1)
void grid_query(const float* __restrict__ S1, float* __restrict__ out)
{
    const int qid = blockIdx.x * QT + threadIdx.x;
    const int b   = qid >> 13;                 // / NQ

    const float* p = S1 + (size_t)qid * 3;
    const float ax = p[0], ay = p[1], az = p[2];
    const float n1 = __fadd_rn(__fadd_rn(__fmul_rn(ax, ax), __fmul_rn(ay, ay)),
                               __fmul_rn(az, az));

    const float ox = g_params[b][0], oy = g_params[b][1], oz = g_params[b][2];
    const float ivx = g_params[b][3], ivy = g_params[b][4], ivz = g_params[b][5];
    const float hmin = g_params[b][6];

    const int cqx = min(GRID - 1, max(0, (int)floorf((ax - ox) * ivx)));
    const int cqy = min(GRID - 1, max(0, (int)floorf((ay - oy) * ivy)));
    const int cqz = min(GRID - 1, max(0, (int)floorf((az - oz) * ivz)));

    const float4* sb = g_sorted[b];
    const int*    st = g_start[b];

    float best = __int_as_float(0x7f800000);
    int   bidx = 0x7fffffff;

    for (int k = 0; k < GRID; ++k) {
        if (k >= 2) {
            float r = (float)(k - 1) * hmin;
            if (r * r > best + SAFETY) break;   // conservative: no unexamined cand can tie/beat
        }
        for (int dz = -k; dz <= k; ++dz) {
            const int z2 = cqz + dz;
            if (z2 < 0 || z2 >= GRID) continue;
            const bool zf = (abs(dz) == k);
            for (int dy = -k; dy <= k; ++dy) {
                const int y2 = cqy + dy;
                if (y2 < 0 || y2 >= GRID) continue;
                const bool yf = zf || (abs(dy) == k);
                const int rowbase = (z2 * GRID + y2) * GRID;
                for (int dx = -k; dx <= k; ++dx) {
                    if (!yf && abs(dx) != k) continue;   // only Chebyshev-ring-k cells
                    const int x2 = cqx + dx;
                    if (x2 < 0 || x2 >= GRID) continue;
                    const int cidc = rowbase + x2;
                    const int s = st[cidc];
                    const int e = st[cidc + 1];
                    for (int i = s; i < e; ++i) {
                        float4 c = sb[i];
                        const int oi = __float_as_int(c.w);
                        float n2 = __fadd_rn(__fadd_rn(__fmul_rn(c.x, c.x),
                                                       __fmul_rn(c.y, c.y)),
                                             __fmul_rn(c.z, c.z));
                        float cr = __fmaf_rn(az, c.z,
                                   __fmaf_rn(ay, c.y, __fmul_rn(ax, c.x)));
                        float d  = __fadd_rn(__fmaf_rn(cr, -2.0f, n1), n2);
                        if (d < best || (d == best && oi < bidx)) { best = d; bidx = oi; }
                    }
                }
            }
        }
    }

    out[qid] = (float)bidx;
}

extern "C" void kernel_launch(void* const* d_in, const int* in_sizes, int n_in,
                              void* d_out, int out_size)
{
    const float* S1 = (const float*)d_in[0];
    const float* S2 = (const float*)d_in[1];
    float* out = (float*)d_out;

    grid_build<<<NBATCH, BT>>>(S2);
    grid_query<<<(NBATCH * NQ) / QT, QT>>>(S1, out);
}